// round 2
// baseline (speedup 1.0000x reference)
#include <cuda_runtime.h>
#include <stdint.h>

// SpikeFP32Embedding: out[t, :, :] = weight_pulse[token_ids[t], :, :]
// token_ids: [16384] int32; weight_pulse: [32768, 128, 32] f32; out: [16384, 128, 32] f32
// Row = 4096 f32 = 1024 float4 = 16 KB.
//
// Strategy: counting-sort tokens by row id so duplicate rows are gathered by
// adjacent CTAs (L2 hit instead of second DRAM fetch), then CTA-per-token copy.

static constexpr int N_TOKENS   = 16384;
static constexpr int N_BINS     = 32768;   // padded vocab
static constexpr int ROW_FLOAT4 = 1024;    // float4 per row
static constexpr int THREADS    = 256;
static constexpr int PER_THREAD = ROW_FLOAT4 / THREADS;  // 4

// Scratch (device globals — no allocation allowed)
__device__ int g_hist[N_BINS];
__device__ int g_off[N_BINS];
__device__ int g_perm[N_TOKENS];   // packed: (row << 14) | token_index

// ---------------------------------------------------------------- zero hist
__global__ void zero_hist_kernel()
{
    int i = blockIdx.x * blockDim.x + threadIdx.x;
    if (i < N_BINS) g_hist[i] = 0;
}

// ---------------------------------------------------------------- histogram
__global__ void hist_kernel(const int* __restrict__ tok, int n)
{
    int t = blockIdx.x * blockDim.x + threadIdx.x;
    if (t < n) atomicAdd(&g_hist[__ldg(tok + t)], 1);
}

// --------------------------------------------------- exclusive scan (1 CTA)
__global__ __launch_bounds__(1024)
void scan_kernel()
{
    __shared__ int sums[1024];
    const int tid  = threadIdx.x;
    const int base = tid * 32;

    int local[32];
    int s = 0;
#pragma unroll
    for (int i = 0; i < 32; ++i) {
        local[i] = s;               // exclusive within chunk
        s += g_hist[base + i];
    }
    sums[tid] = s;
    __syncthreads();

    // Hillis-Steele inclusive scan over the 1024 chunk totals
    for (int off = 1; off < 1024; off <<= 1) {
        int v = (tid >= off) ? sums[tid - off] : 0;
        __syncthreads();
        sums[tid] += v;
        __syncthreads();
    }

    const int prev = (tid == 0) ? 0 : sums[tid - 1];
#pragma unroll
    for (int i = 0; i < 32; ++i)
        g_off[base + i] = prev + local[i];
}

// ---------------------------------------------------------------- scatter
__global__ void scatter_kernel(const int* __restrict__ tok, int n)
{
    int t = blockIdx.x * blockDim.x + threadIdx.x;
    if (t < n) {
        const int row = __ldg(tok + t);
        const int pos = atomicAdd(&g_off[row], 1);
        g_perm[pos] = (row << 14) | t;       // row:15b, t:14b
    }
}

// ---------------------------------------------------------------- gather
__global__ __launch_bounds__(THREADS, 8)
void gather_kernel(const float4* __restrict__ pulse,
                   float4* __restrict__ out)
{
    const int packed = g_perm[blockIdx.x];
    const int t   = packed & (N_TOKENS - 1);
    const int row = packed >> 14;

    const float4* __restrict__ src = pulse + (size_t)row * ROW_FLOAT4 + threadIdx.x;
    float4* __restrict__ dst = out + (size_t)t * ROW_FLOAT4 + threadIdx.x;

    float4 v[PER_THREAD];
#pragma unroll
    for (int i = 0; i < PER_THREAD; ++i)
        v[i] = __ldg(src + i * THREADS);

#pragma unroll
    for (int i = 0; i < PER_THREAD; ++i)
        __stcs(dst + i * THREADS, v[i]);
}

extern "C" void kernel_launch(void* const* d_in, const int* in_sizes, int n_in,
                              void* d_out, int out_size)
{
    const int*    tok   = (const int*)d_in[0];      // [16384]
    const float4* pulse = (const float4*)d_in[1];   // [32768*1024] float4
    float4*       out   = (float4*)d_out;

    const int n = in_sizes[0];                      // 16384

    zero_hist_kernel<<<(N_BINS + 255) / 256, 256>>>();
    hist_kernel<<<(n + 255) / 256, 256>>>(tok, n);
    scan_kernel<<<1, 1024>>>();
    scatter_kernel<<<(n + 255) / 256, 256>>>(tok, n);
    gather_kernel<<<n, THREADS>>>(pulse, out);
}

// round 4
// speedup vs baseline: 1.4107x; 1.4107x over previous
#include <cuda_runtime.h>
#include <stdint.h>

// SpikeFP32Embedding: out[t, :, :] = weight_pulse[token_ids[t], :, :]
// token_ids: [16384] int32; weight_pulse: [32768, 128, 32] f32; out: [16384, 128, 32] f32
// Row = 4096 f32 = 16 KB = 512 x 32B chunks.
//
// Single-kernel gather. 32B reads with L2::evict_last (pin gather rows in L2 so
// duplicate-token re-reads hit); streaming evict-first stores keep the 256MB
// write stream from displacing them. sm_103a requires .v4.b64/.v8.b32 for the
// evict_last modifier — hence 32B loads.

static constexpr int ROW_CHUNKS = 512;    // 32B chunks per row
static constexpr int THREADS    = 256;
static constexpr int PER_THREAD = ROW_CHUNKS / THREADS;  // 2

struct Chunk32 { float4 a, b; };

__device__ __forceinline__ Chunk32 ldg32_evict_last(const void* p)
{
    Chunk32 c;
    asm volatile("ld.global.nc.L2::evict_last.v4.b64 {%0,%1,%2,%3}, [%4];"
                 : "=l"(*reinterpret_cast<unsigned long long*>(&c.a.x)),
                   "=l"(*reinterpret_cast<unsigned long long*>(&c.a.z)),
                   "=l"(*reinterpret_cast<unsigned long long*>(&c.b.x)),
                   "=l"(*reinterpret_cast<unsigned long long*>(&c.b.z))
                 : "l"(p));
    return c;
}

__global__ __launch_bounds__(THREADS, 8)
void spike_embed_gather(const int* __restrict__ tok,
                        const float4* __restrict__ pulse,
                        float4* __restrict__ out)
{
    const int t = blockIdx.x;
    const int row = __ldg(tok + t);

    // thread i handles 32B chunks {i, i+256} of the row (chunk = 2 float4)
    const float4* __restrict__ src = pulse + (size_t)row * (ROW_CHUNKS * 2) + threadIdx.x * 2;
    float4* __restrict__ dst = out + (size_t)t * (ROW_CHUNKS * 2) + threadIdx.x * 2;

    Chunk32 v[PER_THREAD];
#pragma unroll
    for (int i = 0; i < PER_THREAD; ++i)
        v[i] = ldg32_evict_last(src + i * (THREADS * 2));

#pragma unroll
    for (int i = 0; i < PER_THREAD; ++i) {
        __stcs(dst + i * (THREADS * 2) + 0, v[i].a);
        __stcs(dst + i * (THREADS * 2) + 1, v[i].b);
    }
}

extern "C" void kernel_launch(void* const* d_in, const int* in_sizes, int n_in,
                              void* d_out, int out_size)
{
    const int*    tok   = (const int*)d_in[0];      // [16384]
    const float4* pulse = (const float4*)d_in[1];   // [32768*1024] float4
    float4*       out   = (float4*)d_out;

    const int n_tokens = in_sizes[0];               // 16384
    spike_embed_gather<<<n_tokens, THREADS>>>(tok, pulse, out);
}